// round 10
// baseline (speedup 1.0000x reference)
#include <cuda_runtime.h>
#include <cuda_bf16.h>
#include <math.h>
#include <stdint.h>

#define NN 4096
#define HH 32
#define ROLLN 200
#define KSPLITS 8
#define ROWTILES 32            // 4096 / 128
#define NCH_TOT 64             // K chunks of 64 over 4096
#define NCH_PER 8              // chunks per CTA (K=512 per split)
#define ATILE_BYTES 16384      // 128 rows x 64 k x 2B (bf16), SW128 image
#define ATILE_ELEMS 8192
#define BTILE_BYTES 4096       // 32 n x 64 k x 2B
#define BTILE_ELEMS 2048
#define GEMM_THREADS 256
#define UPD_ROWS 16
#define UPD_THREADS 512

// gemm smem layout
#define MB_FULL0 0
#define SMEM_BUF 1024
#define BUF_STRIDE 40960
#define OFF_AHI 0
#define OFF_ALO 16384
#define OFF_BHI 32768
#define OFF_BLO 36864
#define SMEM_DYN (SMEM_BUF + 2 * BUF_STRIDE)   // 82944

// update smem layout (float offsets), pitch 68 for conflict-free f4 loads
#define SW_OFF   0                    // [128][68] combined [W_ih | W_hh]
#define SWT_OFF  (SW_OFF + 128 * 68)  // [32][68] combined [Wh^T | Wc^T]
#define SVEC_OFF (SWT_OFF + 32 * 68)  // [16][68] per-row vectors
#define SMV_OFF  (SVEC_OFF + 16 * 68) // [16][33] transpose buffer
#define SWX_OFF  (SMV_OFF + 16 * 33)  // [5][32]
#define SB_OFF   (SWX_OFF + 160)      // [128]
#define UPD_SMEM_FLOATS (SB_OFF + 128)
#define UPD_SMEM_BYTES (UPD_SMEM_FLOATS * 4)   // ~51.1 KB

// Persistent state (device globals — no allocation allowed)
__device__ float g_h[NN * HH];
__device__ float g_c[NN * HH];
__device__ float g_part[KSPLITS][NN * HH];
__device__ __align__(1024) __nv_bfloat16 g_Ahi[ROWTILES * NCH_TOT * ATILE_ELEMS];
__device__ __align__(1024) __nv_bfloat16 g_Alo[ROWTILES * NCH_TOT * ATILE_ELEMS];
__device__ __align__(1024) __nv_bfloat16 g_Bhi[NCH_TOT * BTILE_ELEMS];
__device__ __align__(1024) __nv_bfloat16 g_Blo[NCH_TOT * BTILE_ELEMS];

__device__ __forceinline__ uint32_t swz(uint32_t b) { return b ^ ((b >> 3) & 0x70); }

__device__ __forceinline__ uint32_t smem_u32(const void* p) {
    uint32_t a;
    asm("{ .reg .u64 t; cvta.to.shared.u64 t, %1; cvt.u32.u64 %0, t; }" : "=r"(a) : "l"(p));
    return a;
}
__device__ __forceinline__ void mbar_init(uint32_t a, uint32_t c) {
    asm volatile("mbarrier.init.shared.b64 [%0], %1;" :: "r"(a), "r"(c) : "memory");
}
__device__ __forceinline__ void mbar_expect(uint32_t a, uint32_t n) {
    asm volatile("mbarrier.arrive.expect_tx.shared.b64 _, [%0], %1;" :: "r"(a), "r"(n) : "memory");
}
__device__ __forceinline__ void mbar_wait(uint32_t mbar, uint32_t parity) {
    asm volatile(
        "{\n\t.reg .pred P1;\n\t"
        "WL_%=:\n\t"
        "mbarrier.try_wait.parity.acquire.cta.shared::cta.b64 P1, [%0], %1, 0x989680;\n\t"
        "@P1 bra.uni WD_%=;\n\t"
        "bra.uni WL_%=;\n\t"
        "WD_%=:\n\t}"
        :: "r"(mbar), "r"(parity) : "memory");
}
__device__ __forceinline__ void bulk_g2s(uint32_t dst, const void* src, uint32_t bytes, uint32_t mbar) {
    asm volatile(
        "cp.async.bulk.shared::cluster.global.mbarrier::complete_tx::bytes [%0], [%1], %2, [%3];"
        :: "r"(dst), "l"(src), "r"(bytes), "r"(mbar) : "memory");
}
__device__ __forceinline__ void ldsm4(uint32_t* r, uint32_t addr) {
    asm volatile("ldmatrix.sync.aligned.m8n8.x4.shared.b16 {%0,%1,%2,%3}, [%4];"
                 : "=r"(r[0]), "=r"(r[1]), "=r"(r[2]), "=r"(r[3]) : "r"(addr));
}
__device__ __forceinline__ void hmma(float* c, const uint32_t* a, uint32_t b0, uint32_t b1) {
    asm volatile(
        "mma.sync.aligned.m16n8k16.row.col.f32.bf16.bf16.f32 "
        "{%0,%1,%2,%3}, {%4,%5,%6,%7}, {%8,%9}, {%0,%1,%2,%3};"
        : "+f"(c[0]), "+f"(c[1]), "+f"(c[2]), "+f"(c[3])
        : "r"(a[0]), "r"(a[1]), "r"(a[2]), "r"(a[3]), "r"(b0), "r"(b1));
}

// ---------------------------------------------------------------------------
// One-time: split A into pre-swizzled, pre-tiled bf16 hi/lo images
// ---------------------------------------------------------------------------
__global__ __launch_bounds__(256) void convA_kernel(const float* __restrict__ A) {
    int idx = blockIdx.x * 256 + threadIdx.x;
    int r = idx >> 12;
    int k = idx & 4095;
    float v = A[idx];
    __nv_bfloat16 hi = __float2bfloat16(v);
    __nv_bfloat16 lo = __float2bfloat16(v - __bfloat162float(hi));
    int tile = (r >> 7) * NCH_TOT + (k >> 6);
    uint32_t off = swz((uint32_t)((r & 127) * 128 + (k & 63) * 2)) >> 1;
    g_Ahi[(size_t)tile * ATILE_ELEMS + off] = hi;
    g_Alo[(size_t)tile * ATILE_ELEMS + off] = lo;
}

// ---------------------------------------------------------------------------
// Init: h = c = 0, M0 = X[0] @ Wx  -> swizzled bf16 hi/lo B tiles
// ---------------------------------------------------------------------------
__global__ __launch_bounds__(256) void init_kernel(const float* __restrict__ X,
                                                   const float* __restrict__ Wx) {
    int idx = blockIdx.x * 256 + threadIdx.x;
    int n = idx >> 5;
    int j = idx & 31;
    g_h[idx] = 0.f;
    g_c[idx] = 0.f;
    float mv = 0.f;
#pragma unroll
    for (int k = 0; k < 5; k++)
        mv += X[n * 5 + k] * Wx[k * HH + j];
    __nv_bfloat16 hi = __float2bfloat16(mv);
    __nv_bfloat16 lo = __float2bfloat16(mv - __bfloat162float(hi));
    int kc = n >> 6;
    uint32_t off = swz((uint32_t)(j * 128 + (n & 63) * 2)) >> 1;
    g_Bhi[kc * BTILE_ELEMS + off] = hi;
    g_Blo[kc * BTILE_ELEMS + off] = lo;
}

// ---------------------------------------------------------------------------
// HMMA GEMM (unchanged structure, KSPLITS=8 for full-SM coverage)
// ---------------------------------------------------------------------------
__device__ __forceinline__ void copy_chunk(uint32_t sb, int b, int rowtile, int chg) {
    uint32_t base = sb + SMEM_BUF + b * BUF_STRIDE;
    uint32_t mbar = sb + MB_FULL0 + b * 8;
    mbar_expect(mbar, 2 * ATILE_BYTES + 2 * BTILE_BYTES);
    bulk_g2s(base + OFF_AHI, g_Ahi + ((size_t)rowtile * NCH_TOT + chg) * ATILE_ELEMS,
             ATILE_BYTES, mbar);
    bulk_g2s(base + OFF_ALO, g_Alo + ((size_t)rowtile * NCH_TOT + chg) * ATILE_ELEMS,
             ATILE_BYTES, mbar);
    bulk_g2s(base + OFF_BHI, g_Bhi + (size_t)chg * BTILE_ELEMS, BTILE_BYTES, mbar);
    bulk_g2s(base + OFF_BLO, g_Blo + (size_t)chg * BTILE_ELEMS, BTILE_BYTES, mbar);
}

__global__ __launch_bounds__(GEMM_THREADS) void gemm_tc() {
    extern __shared__ char smem[];
    uint32_t sb = smem_u32(smem);
    const int tid = threadIdx.x;
    const int wid = tid >> 5;
    const int lid = tid & 31;
    const int rowtile = blockIdx.x;
    const int split = blockIdx.y;

    if (tid == 0) {
        mbar_init(sb + MB_FULL0, 1);
        mbar_init(sb + MB_FULL0 + 8, 1);
    }
    __syncthreads();

    float acc[16];
#pragma unroll
    for (int q = 0; q < 16; q++) acc[q] = 0.f;

    const int arow = (wid << 4) + (lid & 15);
    const uint32_t aRowOff = (uint32_t)arow * 128;
    const uint32_t aSx = (uint32_t)(arow & 7) << 4;
    const uint32_t aHalf = (uint32_t)(lid >> 4) << 4;
    const int bn = ((lid >> 4) << 3) + (lid & 7);
    const uint32_t bRowOff = (uint32_t)bn * 128;
    const uint32_t bSx = (uint32_t)(lid & 7) << 4;
    const uint32_t bHalf = (uint32_t)((lid >> 3) & 1) << 4;

    const int ch0 = split * NCH_PER;
    int fph0 = 0, fph1 = 0;
    if (tid == 0) copy_chunk(sb, 0, rowtile, ch0);

    for (int i = 0; i < NCH_PER; i++) {
        const int b = i & 1;
        if (tid == 0 && i + 1 < NCH_PER)
            copy_chunk(sb, b ^ 1, rowtile, ch0 + i + 1);

        if (b == 0) { mbar_wait(sb + MB_FULL0, fph0); fph0 ^= 1; }
        else        { mbar_wait(sb + MB_FULL0 + 8, fph1); fph1 ^= 1; }

        const uint32_t base = sb + SMEM_BUF + b * BUF_STRIDE;
        const uint32_t aBase = base + OFF_AHI + aRowOff;
        const uint32_t aBaseLo = base + OFF_ALO + aRowOff;
        const uint32_t bBaseHi = base + OFF_BHI + bRowOff;
        const uint32_t bBaseLo = base + OFF_BLO + bRowOff;

#pragma unroll
        for (int ks = 0; ks < 4; ks++) {
            const uint32_t ak = ((uint32_t)(ks << 5) | aHalf) ^ aSx;
            const uint32_t bk = ((uint32_t)(ks << 5) | bHalf) ^ bSx;
            uint32_t ah[4], al[4], bh[8], bl[8];
            ldsm4(ah, aBase + ak);
            ldsm4(al, aBaseLo + ak);
            ldsm4(&bh[0], bBaseHi + bk);
            ldsm4(&bh[4], bBaseHi + 16 * 128 + bk);
            ldsm4(&bl[0], bBaseLo + bk);
            ldsm4(&bl[4], bBaseLo + 16 * 128 + bk);
#pragma unroll
            for (int nt = 0; nt < 4; nt++) {
                float* C = acc + nt * 4;
                hmma(C, ah, bh[2 * nt], bh[2 * nt + 1]);
                hmma(C, ah, bl[2 * nt], bl[2 * nt + 1]);
                hmma(C, al, bh[2 * nt], bh[2 * nt + 1]);
            }
        }
        __syncthreads();
    }

    const int g = lid >> 2, tg = lid & 3;
    const int row = rowtile * 128 + (wid << 4) + g;
    float* op = &g_part[split][0];
#pragma unroll
    for (int nt = 0; nt < 4; nt++) {
        int n = nt * 8 + tg * 2;
        *(float2*)&op[(size_t)row * HH + n]       = make_float2(acc[nt * 4], acc[nt * 4 + 1]);
        *(float2*)&op[(size_t)(row + 8) * HH + n] = make_float2(acc[nt * 4 + 2], acc[nt * 4 + 3]);
    }
}

// ---------------------------------------------------------------------------
// Update (rebuilt): shuffle-free, vectorized, full-SM wave.
// 256 blocks x 512 thr; one warp per node row. Per-row vectors live in smem
// and are read as LDS.128 broadcasts; weights read as float4 from pitch-68
// tiles (conflict-free per 8-lane phase).
// ---------------------------------------------------------------------------
__global__ __launch_bounds__(UPD_THREADS) void update_kernel(
    const float* __restrict__ X,
    const float* __restrict__ Wh,
    const float* __restrict__ Wc,
    const float* __restrict__ Wx,
    const float* __restrict__ W_ih,
    const float* __restrict__ W_hh,
    const float* __restrict__ b_ih,
    const float* __restrict__ b_hh,
    const float* __restrict__ W_fc,
    const float* __restrict__ b_fc,
    float* __restrict__ out,
    int t)
{
    extern __shared__ float S[];
    const int tid = threadIdx.x;

    // Stage combined gate weights sW[q][m]: m<32 -> W_ih[q][m], else W_hh[q][m-32]
    for (int i = tid; i < 128 * 64; i += UPD_THREADS) {
        int q = i >> 6, m = i & 63;
        S[SW_OFF + q * 68 + m] = (m < 32) ? W_ih[q * 32 + m] : W_hh[q * 32 + (m - 32)];
    }
    // Stage transposed recur weights sWT[j][m]: m<32 -> Wh[m][j], else Wc[m-32][j]
    for (int i = tid; i < 32 * 64; i += UPD_THREADS) {
        int jj = i >> 6, m = i & 63;
        S[SWT_OFF + jj * 68 + m] = (m < 32) ? Wh[m * 32 + jj] : Wc[(m - 32) * 32 + jj];
    }
    if (tid < 160) S[SWX_OFF + tid] = Wx[tid];
    if (tid < 128) S[SB_OFF + tid] = b_ih[tid] + b_hh[tid];
    __syncthreads();

    const int j  = tid & 31;
    const int r  = tid >> 5;
    const int n  = blockIdx.x * UPD_ROWS + r;
    const int nj = n * HH + j;

    // Reduce split-K partials (fixed order -> deterministic)
    float x = 0.f;
#pragma unroll
    for (int s = 0; s < KSPLITS; s++) x += g_part[s][nj];
    float hv = g_h[nj];
    float cv = g_c[nj];

    // Publish row vector {x | h} for broadcast reads
    float* vrow = &S[SVEC_OFF + r * 68];
    vrow[j] = x;
    vrow[32 + j] = hv;
    __syncwarp();

    float gi = S[SB_OFF + j], gf = S[SB_OFF + 32 + j],
          gg = S[SB_OFF + 64 + j], go = S[SB_OFF + 96 + j];
    const float* w0 = &S[SW_OFF + j * 68];
    const float* w1 = &S[SW_OFF + (32 + j) * 68];
    const float* w2 = &S[SW_OFF + (64 + j) * 68];
    const float* w3 = &S[SW_OFF + (96 + j) * 68];
#pragma unroll
    for (int q = 0; q < 16; q++) {
        float4 v4 = *(const float4*)&vrow[4 * q];
        float4 a = *(const float4*)&w0[4 * q];
        gi += v4.x * a.x + v4.y * a.y + v4.z * a.z + v4.w * a.w;
        float4 b = *(const float4*)&w1[4 * q];
        gf += v4.x * b.x + v4.y * b.y + v4.z * b.z + v4.w * b.w;
        float4 c = *(const float4*)&w2[4 * q];
        gg += v4.x * c.x + v4.y * c.y + v4.z * c.z + v4.w * c.w;
        float4 d = *(const float4*)&w3[4 * q];
        go += v4.x * d.x + v4.y * d.y + v4.z * d.z + v4.w * d.w;
    }
    float si = 1.f / (1.f + expf(-gi));
    float sf = 1.f / (1.f + expf(-gf));
    float tg = tanhf(gg);
    float so = 1.f / (1.f + expf(-go));
    float cn = sf * cv + si * tg;
    float hn = so * tanhf(cn);
    g_c[nj] = cn;
    g_h[nj] = hn;

    if (t == ROLLN - 1) {
        float v = hn * W_fc[j];
#pragma unroll
        for (int o = 16; o > 0; o >>= 1)
            v += __shfl_xor_sync(0xffffffffu, v, o);
        if (j == 0) out[n] = v + b_fc[0];
    } else {
        // Publish {hn | cn}, then M_next[n][j] = X[t+1]@Wx + hn@Wh + cn@Wc
        __syncwarp();
        vrow[j] = hn;
        vrow[32 + j] = cn;
        __syncwarp();

        const float* xr = X + ((size_t)(t + 1) * NN + n) * 5;
        float mv = 0.f;
#pragma unroll
        for (int k = 0; k < 5; k++) mv += xr[k] * S[SWX_OFF + k * 32 + j];
        const float* wt = &S[SWT_OFF + j * 68];
#pragma unroll
        for (int q = 0; q < 16; q++) {
            float4 v4 = *(const float4*)&vrow[4 * q];
            float4 w = *(const float4*)&wt[4 * q];
            mv += v4.x * w.x + v4.y * w.y + v4.z * w.z + v4.w * w.w;
        }

        // Transpose through smem so bf16 tile stores are contiguous
        S[SMV_OFF + r * 33 + j] = mv;
        __syncthreads();
        int j2 = tid >> 4, nn = tid & 15;
        int n2 = blockIdx.x * UPD_ROWS + nn;
        float tv = S[SMV_OFF + nn * 33 + j2];
        __nv_bfloat16 hi = __float2bfloat16(tv);
        __nv_bfloat16 lo = __float2bfloat16(tv - __bfloat162float(hi));
        int kc = n2 >> 6;
        uint32_t off = swz((uint32_t)(j2 * 128 + (n2 & 63) * 2)) >> 1;
        g_Bhi[kc * BTILE_ELEMS + off] = hi;
        g_Blo[kc * BTILE_ELEMS + off] = lo;
    }
}

// ---------------------------------------------------------------------------
extern "C" void kernel_launch(void* const* d_in, const int* in_sizes, int n_in,
                              void* d_out, int out_size) {
    const float* X    = (const float*)d_in[0];
    const float* A    = (const float*)d_in[1];
    const float* Wx   = (const float*)d_in[2];
    const float* Wh   = (const float*)d_in[3];
    const float* Wc   = (const float*)d_in[4];
    const float* W_ih = (const float*)d_in[5];
    const float* W_hh = (const float*)d_in[6];
    const float* b_ih = (const float*)d_in[7];
    const float* b_hh = (const float*)d_in[8];
    const float* W_fc = (const float*)d_in[9];
    const float* b_fc = (const float*)d_in[10];
    float* out = (float*)d_out;

    cudaFuncSetAttribute(gemm_tc, cudaFuncAttributeMaxDynamicSharedMemorySize, SMEM_DYN);
    cudaFuncSetAttribute(update_kernel, cudaFuncAttributeMaxDynamicSharedMemorySize, UPD_SMEM_BYTES);

    convA_kernel<<<(NN * NN) / 256, 256>>>(A);
    init_kernel<<<(NN * HH) / 256, 256>>>(X, Wx);

    dim3 ggrid(ROWTILES, KSPLITS);
    for (int t = 0; t < ROLLN; t++) {
        gemm_tc<<<ggrid, GEMM_THREADS, SMEM_DYN>>>();
        update_kernel<<<NN / UPD_ROWS, UPD_THREADS, UPD_SMEM_BYTES>>>(
            X, Wh, Wc, Wx, W_ih, W_hh, b_ih, b_hh, W_fc, b_fc, out, t);
    }
}

// round 11
// speedup vs baseline: 1.2182x; 1.2182x over previous
#include <cuda_runtime.h>
#include <cuda_bf16.h>
#include <math.h>
#include <stdint.h>

#define NN 4096
#define HH 32
#define ROLLN 200
#define KSPLITS 8
#define ROWTILES 32            // 4096 / 128
#define NCH_TOT 64             // K chunks of 64 over 4096
#define NCH_PER 8              // chunks per CTA (K=512 per split)
#define ATILE_BYTES 16384      // 128 rows x 64 k x 2B (bf16), SW128 image
#define ATILE_ELEMS 8192
#define BTILE_BYTES 4096       // 32 n x 64 k x 2B
#define BTILE_ELEMS 2048
#define GEMM_THREADS 256

// update config: 128 blocks x 256 thr; 8 warps x 4 rows = 32 rows/block
#define UPD_BLOCKS 128
#define UPD_THREADS 256
#define UPD_BLKROWS 32

// gemm smem layout
#define MB_FULL0 0
#define SMEM_BUF 1024
#define BUF_STRIDE 40960
#define OFF_AHI 0
#define OFF_ALO 16384
#define OFF_BHI 32768
#define OFF_BLO 36864
#define SMEM_DYN (SMEM_BUF + 2 * BUF_STRIDE)   // 82944

// update smem layout (float offsets); pitch 68 keeps 16B alignment (68%4==0)
#define SW_OFF   0                     // [128][68]  combined [W_ih | W_hh]
#define SWT_OFF  (SW_OFF + 128 * 68)   // [32][68]   combined [Wh^T | Wc^T]
#define SV_OFF   (SWT_OFF + 32 * 68)   // [32][68]   per-row vectors
#define SMV_OFF  (SV_OFF + 32 * 68)    // [32][33]   transpose buffer
#define SWX_OFF  (SMV_OFF + 32 * 33)   // [5][32]
#define SB_OFF   (SWX_OFF + 160)       // [128]
#define UPD_SMEM_FLOATS (SB_OFF + 128)
#define UPD_SMEM_BYTES  (UPD_SMEM_FLOATS * 4)

// Persistent state (device globals — no allocation allowed)
__device__ float g_h[NN * HH];
__device__ float g_c[NN * HH];
__device__ float g_part[KSPLITS][NN * HH];
__device__ __align__(1024) __nv_bfloat16 g_Ahi[ROWTILES * NCH_TOT * ATILE_ELEMS];
__device__ __align__(1024) __nv_bfloat16 g_Alo[ROWTILES * NCH_TOT * ATILE_ELEMS];
__device__ __align__(1024) __nv_bfloat16 g_Bhi[NCH_TOT * BTILE_ELEMS];
__device__ __align__(1024) __nv_bfloat16 g_Blo[NCH_TOT * BTILE_ELEMS];
// one-time packed weight images (pitch 68, 16B-aligned rows)
__device__ __align__(16) float g_Wg[128 * 68];
__device__ __align__(16) float g_WT[32 * 68];
__device__ float g_bias[128];
__device__ float g_Wxp[160];

__device__ __forceinline__ uint32_t swz(uint32_t b) { return b ^ ((b >> 3) & 0x70); }

__device__ __forceinline__ uint32_t smem_u32(const void* p) {
    uint32_t a;
    asm("{ .reg .u64 t; cvta.to.shared.u64 t, %1; cvt.u32.u64 %0, t; }" : "=r"(a) : "l"(p));
    return a;
}
__device__ __forceinline__ void mbar_init(uint32_t a, uint32_t c) {
    asm volatile("mbarrier.init.shared.b64 [%0], %1;" :: "r"(a), "r"(c) : "memory");
}
__device__ __forceinline__ void mbar_expect(uint32_t a, uint32_t n) {
    asm volatile("mbarrier.arrive.expect_tx.shared.b64 _, [%0], %1;" :: "r"(a), "r"(n) : "memory");
}
__device__ __forceinline__ void mbar_wait(uint32_t mbar, uint32_t parity) {
    asm volatile(
        "{\n\t.reg .pred P1;\n\t"
        "WL_%=:\n\t"
        "mbarrier.try_wait.parity.acquire.cta.shared::cta.b64 P1, [%0], %1, 0x989680;\n\t"
        "@P1 bra.uni WD_%=;\n\t"
        "bra.uni WL_%=;\n\t"
        "WD_%=:\n\t}"
        :: "r"(mbar), "r"(parity) : "memory");
}
__device__ __forceinline__ void bulk_g2s(uint32_t dst, const void* src, uint32_t bytes, uint32_t mbar) {
    asm volatile(
        "cp.async.bulk.shared::cluster.global.mbarrier::complete_tx::bytes [%0], [%1], %2, [%3];"
        :: "r"(dst), "l"(src), "r"(bytes), "r"(mbar) : "memory");
}
__device__ __forceinline__ void ldsm4(uint32_t* r, uint32_t addr) {
    asm volatile("ldmatrix.sync.aligned.m8n8.x4.shared.b16 {%0,%1,%2,%3}, [%4];"
                 : "=r"(r[0]), "=r"(r[1]), "=r"(r[2]), "=r"(r[3]) : "r"(addr));
}
__device__ __forceinline__ void hmma(float* c, const uint32_t* a, uint32_t b0, uint32_t b1) {
    asm volatile(
        "mma.sync.aligned.m16n8k16.row.col.f32.bf16.bf16.f32 "
        "{%0,%1,%2,%3}, {%4,%5,%6,%7}, {%8,%9}, {%0,%1,%2,%3};"
        : "+f"(c[0]), "+f"(c[1]), "+f"(c[2]), "+f"(c[3])
        : "r"(a[0]), "r"(a[1]), "r"(a[2]), "r"(a[3]), "r"(b0), "r"(b1));
}
__device__ __forceinline__ void fma2(unsigned long long& acc, unsigned long long a,
                                     unsigned long long b) {
    asm("fma.rn.f32x2 %0, %1, %2, %0;" : "+l"(acc) : "l"(a), "l"(b));
}
__device__ __forceinline__ float pairsum(unsigned long long u) {
    return __uint_as_float((unsigned)u) + __uint_as_float((unsigned)(u >> 32));
}
__device__ __forceinline__ float sigf(float v) { return 1.f / (1.f + __expf(-v)); }
__device__ __forceinline__ float tanhfast(float v) { return 2.f / (1.f + __expf(-2.f * v)) - 1.f; }

// ---------------------------------------------------------------------------
// One-time: split A into pre-swizzled, pre-tiled bf16 hi/lo images
// ---------------------------------------------------------------------------
__global__ __launch_bounds__(256) void convA_kernel(const float* __restrict__ A) {
    int idx = blockIdx.x * 256 + threadIdx.x;
    int r = idx >> 12;
    int k = idx & 4095;
    float v = A[idx];
    __nv_bfloat16 hi = __float2bfloat16(v);
    __nv_bfloat16 lo = __float2bfloat16(v - __bfloat162float(hi));
    int tile = (r >> 7) * NCH_TOT + (k >> 6);
    uint32_t off = swz((uint32_t)((r & 127) * 128 + (k & 63) * 2)) >> 1;
    g_Ahi[(size_t)tile * ATILE_ELEMS + off] = hi;
    g_Alo[(size_t)tile * ATILE_ELEMS + off] = lo;
}

// ---------------------------------------------------------------------------
// One-time: pack update weights into combined pitch-68 images
// ---------------------------------------------------------------------------
__global__ __launch_bounds__(256) void pack_kernel(
    const float* __restrict__ Wh, const float* __restrict__ Wc,
    const float* __restrict__ Wx,
    const float* __restrict__ W_ih, const float* __restrict__ W_hh,
    const float* __restrict__ b_ih, const float* __restrict__ b_hh)
{
    int idx = blockIdx.x * 256 + threadIdx.x;
    if (idx < 128 * 64) {
        int q = idx >> 6, m = idx & 63;
        g_Wg[q * 68 + m] = (m < 32) ? W_ih[q * 32 + m] : W_hh[q * 32 + (m - 32)];
    } else if (idx < 128 * 64 + 32 * 64) {
        int i = idx - 128 * 64;
        int j = i >> 6, m = i & 63;
        g_WT[j * 68 + m] = (m < 32) ? Wh[m * 32 + j] : Wc[(m - 32) * 32 + j];
    } else if (idx < 128 * 64 + 32 * 64 + 128) {
        int q = idx - (128 * 64 + 32 * 64);
        g_bias[q] = b_ih[q] + b_hh[q];
    } else if (idx < 128 * 64 + 32 * 64 + 128 + 160) {
        int q = idx - (128 * 64 + 32 * 64 + 128);
        g_Wxp[q] = Wx[q];
    }
}

// ---------------------------------------------------------------------------
// Init: h = c = 0, M0 = X[0] @ Wx  -> swizzled bf16 hi/lo B tiles
// ---------------------------------------------------------------------------
__global__ __launch_bounds__(256) void init_kernel(const float* __restrict__ X,
                                                   const float* __restrict__ Wx) {
    int idx = blockIdx.x * 256 + threadIdx.x;
    int n = idx >> 5;
    int j = idx & 31;
    g_h[idx] = 0.f;
    g_c[idx] = 0.f;
    float mv = 0.f;
#pragma unroll
    for (int k = 0; k < 5; k++)
        mv += X[n * 5 + k] * Wx[k * HH + j];
    __nv_bfloat16 hi = __float2bfloat16(mv);
    __nv_bfloat16 lo = __float2bfloat16(mv - __bfloat162float(hi));
    int kc = n >> 6;
    uint32_t off = swz((uint32_t)(j * 128 + (n & 63) * 2)) >> 1;
    g_Bhi[kc * BTILE_ELEMS + off] = hi;
    g_Blo[kc * BTILE_ELEMS + off] = lo;
}

// ---------------------------------------------------------------------------
// HMMA GEMM (unchanged from round 10; at the L2-streaming floor)
// ---------------------------------------------------------------------------
__device__ __forceinline__ void copy_chunk(uint32_t sb, int b, int rowtile, int chg) {
    uint32_t base = sb + SMEM_BUF + b * BUF_STRIDE;
    uint32_t mbar = sb + MB_FULL0 + b * 8;
    mbar_expect(mbar, 2 * ATILE_BYTES + 2 * BTILE_BYTES);
    bulk_g2s(base + OFF_AHI, g_Ahi + ((size_t)rowtile * NCH_TOT + chg) * ATILE_ELEMS,
             ATILE_BYTES, mbar);
    bulk_g2s(base + OFF_ALO, g_Alo + ((size_t)rowtile * NCH_TOT + chg) * ATILE_ELEMS,
             ATILE_BYTES, mbar);
    bulk_g2s(base + OFF_BHI, g_Bhi + (size_t)chg * BTILE_ELEMS, BTILE_BYTES, mbar);
    bulk_g2s(base + OFF_BLO, g_Blo + (size_t)chg * BTILE_ELEMS, BTILE_BYTES, mbar);
}

__global__ __launch_bounds__(GEMM_THREADS) void gemm_tc() {
    extern __shared__ char smem[];
    uint32_t sb = smem_u32(smem);
    const int tid = threadIdx.x;
    const int wid = tid >> 5;
    const int lid = tid & 31;
    const int rowtile = blockIdx.x;
    const int split = blockIdx.y;

    if (tid == 0) {
        mbar_init(sb + MB_FULL0, 1);
        mbar_init(sb + MB_FULL0 + 8, 1);
    }
    __syncthreads();

    float acc[16];
#pragma unroll
    for (int q = 0; q < 16; q++) acc[q] = 0.f;

    const int arow = (wid << 4) + (lid & 15);
    const uint32_t aRowOff = (uint32_t)arow * 128;
    const uint32_t aSx = (uint32_t)(arow & 7) << 4;
    const uint32_t aHalf = (uint32_t)(lid >> 4) << 4;
    const int bn = ((lid >> 4) << 3) + (lid & 7);
    const uint32_t bRowOff = (uint32_t)bn * 128;
    const uint32_t bSx = (uint32_t)(lid & 7) << 4;
    const uint32_t bHalf = (uint32_t)((lid >> 3) & 1) << 4;

    const int ch0 = split * NCH_PER;
    int fph0 = 0, fph1 = 0;
    if (tid == 0) copy_chunk(sb, 0, rowtile, ch0);

    for (int i = 0; i < NCH_PER; i++) {
        const int b = i & 1;
        if (tid == 0 && i + 1 < NCH_PER)
            copy_chunk(sb, b ^ 1, rowtile, ch0 + i + 1);

        if (b == 0) { mbar_wait(sb + MB_FULL0, fph0); fph0 ^= 1; }
        else        { mbar_wait(sb + MB_FULL0 + 8, fph1); fph1 ^= 1; }

        const uint32_t base = sb + SMEM_BUF + b * BUF_STRIDE;
        const uint32_t aBase = base + OFF_AHI + aRowOff;
        const uint32_t aBaseLo = base + OFF_ALO + aRowOff;
        const uint32_t bBaseHi = base + OFF_BHI + bRowOff;
        const uint32_t bBaseLo = base + OFF_BLO + bRowOff;

#pragma unroll
        for (int ks = 0; ks < 4; ks++) {
            const uint32_t ak = ((uint32_t)(ks << 5) | aHalf) ^ aSx;
            const uint32_t bk = ((uint32_t)(ks << 5) | bHalf) ^ bSx;
            uint32_t ah[4], al[4], bh[8], bl[8];
            ldsm4(ah, aBase + ak);
            ldsm4(al, aBaseLo + ak);
            ldsm4(&bh[0], bBaseHi + bk);
            ldsm4(&bh[4], bBaseHi + 16 * 128 + bk);
            ldsm4(&bl[0], bBaseLo + bk);
            ldsm4(&bl[4], bBaseLo + 16 * 128 + bk);
#pragma unroll
            for (int nt = 0; nt < 4; nt++) {
                float* C = acc + nt * 4;
                hmma(C, ah, bh[2 * nt], bh[2 * nt + 1]);
                hmma(C, ah, bl[2 * nt], bl[2 * nt + 1]);
                hmma(C, al, bh[2 * nt], bh[2 * nt + 1]);
            }
        }
        __syncthreads();
    }

    const int g = lid >> 2, tg = lid & 3;
    const int row = rowtile * 128 + (wid << 4) + g;
    float* op = &g_part[split][0];
#pragma unroll
    for (int nt = 0; nt < 4; nt++) {
        int n = nt * 8 + tg * 2;
        *(float2*)&op[(size_t)row * HH + n]       = make_float2(acc[nt * 4], acc[nt * 4 + 1]);
        *(float2*)&op[(size_t)(row + 8) * HH + n] = make_float2(acc[nt * 4 + 2], acc[nt * 4 + 3]);
    }
}

// ---------------------------------------------------------------------------
// Update (R=4 row-blocked, FFMA2): 128 blocks x 256 thr; warp handles 4 rows.
// Weight smem traffic amortized 4x; inner loops are fma.f32x2-dense using the
// natural 64-bit halves of LDS.128s. Fast MUFU-based nonlinearities.
// ---------------------------------------------------------------------------
__global__ __launch_bounds__(UPD_THREADS) void update_kernel(
    const float* __restrict__ X,
    const float* __restrict__ W_fc,
    const float* __restrict__ b_fc,
    float* __restrict__ out,
    int t)
{
    extern __shared__ float S[];
    const int tid = threadIdx.x;
    const int w = tid >> 5;
    const int j = tid & 31;
    const int row0 = blockIdx.x * UPD_BLKROWS + w * 4;

    // ---- Prefetch this warp's row data first (hide L2 latency behind staging)
    float x[4], hv[4], cv[4];
#pragma unroll
    for (int i = 0; i < 4; i++) {
        const int nj = (row0 + i) * HH + j;
        float s0 = g_part[0][nj] + g_part[1][nj];
        float s1 = g_part[2][nj] + g_part[3][nj];
        float s2 = g_part[4][nj] + g_part[5][nj];
        float s3 = g_part[6][nj] + g_part[7][nj];
        x[i] = (s0 + s1) + (s2 + s3);
        hv[i] = g_h[nj];
        cv[i] = g_c[nj];
    }

    // ---- Stage packed weights (straight float4 copies)
    {
        const float4* s1 = (const float4*)g_Wg;
        float4* d1 = (float4*)&S[SW_OFF];
        for (int i = tid; i < 128 * 17; i += UPD_THREADS) d1[i] = s1[i];
        const float4* s2 = (const float4*)g_WT;
        float4* d2 = (float4*)&S[SWT_OFF];
        for (int i = tid; i < 32 * 17; i += UPD_THREADS) d2[i] = s2[i];
        if (tid < 160) S[SWX_OFF + tid] = g_Wxp[tid];
        if (tid < 128) S[SB_OFF + tid] = g_bias[tid];
    }

    // ---- Publish row vectors {x | h} (warp-private rows)
#pragma unroll
    for (int i = 0; i < 4; i++) {
        S[SV_OFF + (w * 4 + i) * 68 + j] = x[i];
        S[SV_OFF + (w * 4 + i) * 68 + 32 + j] = hv[i];
    }
    __syncthreads();   // weights + vectors ready

    // ---- Gates: acc2[i][g], halves = even/odd-m partial sums
    unsigned long long acc[4][4];
#pragma unroll
    for (int i = 0; i < 4; i++)
#pragma unroll
        for (int g = 0; g < 4; g++) acc[i][g] = 0ull;

#pragma unroll
    for (int q = 0; q < 16; q++) {
        ulonglong2 vv[4], ww[4];
#pragma unroll
        for (int i = 0; i < 4; i++)
            vv[i] = *(const ulonglong2*)&S[SV_OFF + (w * 4 + i) * 68 + 4 * q];
#pragma unroll
        for (int g = 0; g < 4; g++)
            ww[g] = *(const ulonglong2*)&S[SW_OFF + (g * 32 + j) * 68 + 4 * q];
#pragma unroll
        for (int i = 0; i < 4; i++)
#pragma unroll
            for (int g = 0; g < 4; g++) {
                fma2(acc[i][g], vv[i].x, ww[g].x);
                fma2(acc[i][g], vv[i].y, ww[g].y);
            }
    }

    // ---- Nonlinearities + state update
    float hn[4], cn[4];
#pragma unroll
    for (int i = 0; i < 4; i++) {
        float gi = pairsum(acc[i][0]) + S[SB_OFF + j];
        float gf = pairsum(acc[i][1]) + S[SB_OFF + 32 + j];
        float gg = pairsum(acc[i][2]) + S[SB_OFF + 64 + j];
        float go = pairsum(acc[i][3]) + S[SB_OFF + 96 + j];
        float si = sigf(gi), sf = sigf(gf), tg = tanhfast(gg), so = sigf(go);
        cn[i] = sf * cv[i] + si * tg;
        hn[i] = so * tanhfast(cn[i]);
        const int nj = (row0 + i) * HH + j;
        g_c[nj] = cn[i];
        g_h[nj] = hn[i];
    }

    if (t == ROLLN - 1) {
#pragma unroll
        for (int i = 0; i < 4; i++) {
            float v = hn[i] * W_fc[j];
#pragma unroll
            for (int o = 16; o > 0; o >>= 1)
                v += __shfl_xor_sync(0xffffffffu, v, o);
            if (j == 0) out[row0 + i] = v + b_fc[0];
        }
    } else {
        // ---- Republish {hn | cn}
        __syncwarp();
#pragma unroll
        for (int i = 0; i < 4; i++) {
            S[SV_OFF + (w * 4 + i) * 68 + j] = hn[i];
            S[SV_OFF + (w * 4 + i) * 68 + 32 + j] = cn[i];
        }
        __syncwarp();

        // ---- M_next = X[t+1]@Wx + hn@Wh + cn@Wc
        float mv[4];
#pragma unroll
        for (int i = 0; i < 4; i++) {
            const float* xr = X + ((size_t)(t + 1) * NN + row0 + i) * 5;
            float s = xr[0] * S[SWX_OFF + j];
            s += xr[1] * S[SWX_OFF + 32 + j];
            s += xr[2] * S[SWX_OFF + 64 + j];
            s += xr[3] * S[SWX_OFF + 96 + j];
            s += xr[4] * S[SWX_OFF + 128 + j];
            mv[i] = s;
        }
        unsigned long long am[4] = {0ull, 0ull, 0ull, 0ull};
#pragma unroll
        for (int q = 0; q < 16; q++) {
            ulonglong2 wt = *(const ulonglong2*)&S[SWT_OFF + j * 68 + 4 * q];
#pragma unroll
            for (int i = 0; i < 4; i++) {
                ulonglong2 vv = *(const ulonglong2*)&S[SV_OFF + (w * 4 + i) * 68 + 4 * q];
                fma2(am[i], vv.x, wt.x);
                fma2(am[i], vv.y, wt.y);
            }
        }
#pragma unroll
        for (int i = 0; i < 4; i++) {
            mv[i] += pairsum(am[i]);
            S[SMV_OFF + (w * 4 + i) * 33 + j] = mv[i];
        }
        __syncthreads();

        // ---- Transposed bf16 hi/lo B-tile stores (contiguous per warp)
#pragma unroll
        for (int k = 0; k < 4; k++) {
            int idx = tid + k * UPD_THREADS;      // 0..1023
            int j2 = idx >> 5, nn = idx & 31;
            float tv = S[SMV_OFF + nn * 33 + j2];
            int n2 = blockIdx.x * UPD_BLKROWS + nn;
            __nv_bfloat16 hi = __float2bfloat16(tv);
            __nv_bfloat16 lo = __float2bfloat16(tv - __bfloat162float(hi));
            int kc = n2 >> 6;
            uint32_t off = swz((uint32_t)(j2 * 128 + (n2 & 63) * 2)) >> 1;
            g_Bhi[kc * BTILE_ELEMS + off] = hi;
            g_Blo[kc * BTILE_ELEMS + off] = lo;
        }
    }
}

// ---------------------------------------------------------------------------
extern "C" void kernel_launch(void* const* d_in, const int* in_sizes, int n_in,
                              void* d_out, int out_size) {
    const float* X    = (const float*)d_in[0];
    const float* A    = (const float*)d_in[1];
    const float* Wx   = (const float*)d_in[2];
    const float* Wh   = (const float*)d_in[3];
    const float* Wc   = (const float*)d_in[4];
    const float* W_ih = (const float*)d_in[5];
    const float* W_hh = (const float*)d_in[6];
    const float* b_ih = (const float*)d_in[7];
    const float* b_hh = (const float*)d_in[8];
    const float* W_fc = (const float*)d_in[9];
    const float* b_fc = (const float*)d_in[10];
    float* out = (float*)d_out;

    cudaFuncSetAttribute(gemm_tc, cudaFuncAttributeMaxDynamicSharedMemorySize, SMEM_DYN);
    cudaFuncSetAttribute(update_kernel, cudaFuncAttributeMaxDynamicSharedMemorySize, UPD_SMEM_BYTES);

    convA_kernel<<<(NN * NN) / 256, 256>>>(A);
    pack_kernel<<<42, 256>>>(Wh, Wc, Wx, W_ih, W_hh, b_ih, b_hh);
    init_kernel<<<(NN * HH) / 256, 256>>>(X, Wx);

    dim3 ggrid(ROWTILES, KSPLITS);
    for (int t = 0; t < ROLLN; t++) {
        gemm_tc<<<ggrid, GEMM_THREADS, SMEM_DYN>>>();
        update_kernel<<<UPD_BLOCKS, UPD_THREADS, UPD_SMEM_BYTES>>>(
            X, W_fc, b_fc, out, t);
    }
}

// round 12
// speedup vs baseline: 1.2724x; 1.0445x over previous
#include <cuda_runtime.h>
#include <cuda_bf16.h>
#include <math.h>
#include <stdint.h>

#define NN 4096
#define HH 32
#define ROLLN 200
#define KSPLITS 8
#define ROWTILES 32            // 4096 / 128
#define NCH_TOT 64             // K chunks of 64 over 4096
#define NCH_PER 8              // chunks per CTA (K=512 per split)
#define ATILE_BYTES 16384      // 128 rows x 64 k x 2B (bf16), SW128 image
#define ATILE_ELEMS 8192
#define BTILE_BYTES 4096       // 32 n x 64 k x 2B
#define BTILE_ELEMS 2048
#define GEMM_THREADS 256

// update config: 128 blocks x 256 thr; 8 warps x 4 rows = 32 rows/block
#define UPD_BLOCKS 128
#define UPD_THREADS 256
#define UPD_BLKROWS 32

// gemm smem layout
#define MB_FULL0 0
#define SMEM_BUF 1024
#define BUF_STRIDE 40960
#define OFF_AHI 0
#define OFF_ALO 16384
#define OFF_BHI 32768
#define OFF_BLO 36864
#define SMEM_DYN (SMEM_BUF + 2 * BUF_STRIDE)   // 82944

// update smem layout (float offsets); pitch 68 keeps 16B alignment (68%4==0)
#define SW_OFF   0                     // [128][68]  combined [W_ih | W_hh]
#define SWT_OFF  (SW_OFF + 128 * 68)   // [32][68]   combined [Wh^T | Wc^T]
#define SV_OFF   (SWT_OFF + 32 * 68)   // [32][68]   per-row vectors
#define SMV_OFF  (SV_OFF + 32 * 68)    // [32][33]   transpose buffer
#define SWX_OFF  (SMV_OFF + 32 * 33)   // [5][32]
#define SB_OFF   (SWX_OFF + 160)       // [128]
#define UPD_SMEM_FLOATS (SB_OFF + 128)
#define UPD_SMEM_BYTES  (UPD_SMEM_FLOATS * 4)

// Persistent state (device globals — no allocation allowed)
__device__ float g_h[NN * HH];
__device__ float g_c[NN * HH];
__device__ float g_part[KSPLITS][NN * HH];
__device__ __align__(1024) __nv_bfloat16 g_Ahi[ROWTILES * NCH_TOT * ATILE_ELEMS];
__device__ __align__(1024) __nv_bfloat16 g_Alo[ROWTILES * NCH_TOT * ATILE_ELEMS];
__device__ __align__(1024) __nv_bfloat16 g_Bhi[NCH_TOT * BTILE_ELEMS];
__device__ __align__(1024) __nv_bfloat16 g_Blo[NCH_TOT * BTILE_ELEMS];
// one-time packed weight images (pitch 68, 16B-aligned rows)
__device__ __align__(16) float g_Wg[128 * 68];
__device__ __align__(16) float g_WT[32 * 68];
__device__ float g_bias[128];
__device__ float g_Wxp[160];

__device__ __forceinline__ uint32_t swz(uint32_t b) { return b ^ ((b >> 3) & 0x70); }

__device__ __forceinline__ uint32_t smem_u32(const void* p) {
    uint32_t a;
    asm("{ .reg .u64 t; cvta.to.shared.u64 t, %1; cvt.u32.u64 %0, t; }" : "=r"(a) : "l"(p));
    return a;
}
__device__ __forceinline__ void mbar_init(uint32_t a, uint32_t c) {
    asm volatile("mbarrier.init.shared.b64 [%0], %1;" :: "r"(a), "r"(c) : "memory");
}
__device__ __forceinline__ void mbar_expect(uint32_t a, uint32_t n) {
    asm volatile("mbarrier.arrive.expect_tx.shared.b64 _, [%0], %1;" :: "r"(a), "r"(n) : "memory");
}
__device__ __forceinline__ void mbar_wait(uint32_t mbar, uint32_t parity) {
    asm volatile(
        "{\n\t.reg .pred P1;\n\t"
        "WL_%=:\n\t"
        "mbarrier.try_wait.parity.acquire.cta.shared::cta.b64 P1, [%0], %1, 0x989680;\n\t"
        "@P1 bra.uni WD_%=;\n\t"
        "bra.uni WL_%=;\n\t"
        "WD_%=:\n\t}"
        :: "r"(mbar), "r"(parity) : "memory");
}
// evict_last policy: A images get L2 residency priority so every step after
// the first reads them from L2 (~11 TB/s LTS path) instead of HBM.
__device__ __forceinline__ uint64_t mkpol_evict_last() {
    uint64_t p;
    asm("createpolicy.fractional.L2::evict_last.b64 %0, 1.0;" : "=l"(p));
    return p;
}
__device__ __forceinline__ void bulk_g2s_hint(uint32_t dst, const void* src, uint32_t bytes,
                                              uint32_t mbar, uint64_t pol) {
    asm volatile(
        "cp.async.bulk.shared::cluster.global.mbarrier::complete_tx::bytes.L2::cache_hint "
        "[%0], [%1], %2, [%3], %4;"
        :: "r"(dst), "l"(src), "r"(bytes), "r"(mbar), "l"(pol) : "memory");
}
__device__ __forceinline__ void ldsm4(uint32_t* r, uint32_t addr) {
    asm volatile("ldmatrix.sync.aligned.m8n8.x4.shared.b16 {%0,%1,%2,%3}, [%4];"
                 : "=r"(r[0]), "=r"(r[1]), "=r"(r[2]), "=r"(r[3]) : "r"(addr));
}
__device__ __forceinline__ void hmma(float* c, const uint32_t* a, uint32_t b0, uint32_t b1) {
    asm volatile(
        "mma.sync.aligned.m16n8k16.row.col.f32.bf16.bf16.f32 "
        "{%0,%1,%2,%3}, {%4,%5,%6,%7}, {%8,%9}, {%0,%1,%2,%3};"
        : "+f"(c[0]), "+f"(c[1]), "+f"(c[2]), "+f"(c[3])
        : "r"(a[0]), "r"(a[1]), "r"(a[2]), "r"(a[3]), "r"(b0), "r"(b1));
}
__device__ __forceinline__ void fma2(unsigned long long& acc, unsigned long long a,
                                     unsigned long long b) {
    asm("fma.rn.f32x2 %0, %1, %2, %0;" : "+l"(acc) : "l"(a), "l"(b));
}
__device__ __forceinline__ float pairsum(unsigned long long u) {
    return __uint_as_float((unsigned)u) + __uint_as_float((unsigned)(u >> 32));
}
__device__ __forceinline__ float sigf(float v) { return 1.f / (1.f + __expf(-v)); }
__device__ __forceinline__ float tanhfast(float v) { return 2.f / (1.f + __expf(-2.f * v)) - 1.f; }

// ---------------------------------------------------------------------------
// One-time: split A into pre-swizzled, pre-tiled bf16 hi/lo images
// ---------------------------------------------------------------------------
__global__ __launch_bounds__(256) void convA_kernel(const float* __restrict__ A) {
    int idx = blockIdx.x * 256 + threadIdx.x;
    int r = idx >> 12;
    int k = idx & 4095;
    float v = A[idx];
    __nv_bfloat16 hi = __float2bfloat16(v);
    __nv_bfloat16 lo = __float2bfloat16(v - __bfloat162float(hi));
    int tile = (r >> 7) * NCH_TOT + (k >> 6);
    uint32_t off = swz((uint32_t)((r & 127) * 128 + (k & 63) * 2)) >> 1;
    g_Ahi[(size_t)tile * ATILE_ELEMS + off] = hi;
    g_Alo[(size_t)tile * ATILE_ELEMS + off] = lo;
}

// ---------------------------------------------------------------------------
// One-time: pack update weights into combined pitch-68 images
// ---------------------------------------------------------------------------
__global__ __launch_bounds__(256) void pack_kernel(
    const float* __restrict__ Wh, const float* __restrict__ Wc,
    const float* __restrict__ Wx,
    const float* __restrict__ W_ih, const float* __restrict__ W_hh,
    const float* __restrict__ b_ih, const float* __restrict__ b_hh)
{
    int idx = blockIdx.x * 256 + threadIdx.x;
    if (idx < 128 * 64) {
        int q = idx >> 6, m = idx & 63;
        g_Wg[q * 68 + m] = (m < 32) ? W_ih[q * 32 + m] : W_hh[q * 32 + (m - 32)];
    } else if (idx < 128 * 64 + 32 * 64) {
        int i = idx - 128 * 64;
        int j = i >> 6, m = i & 63;
        g_WT[j * 68 + m] = (m < 32) ? Wh[m * 32 + j] : Wc[(m - 32) * 32 + j];
    } else if (idx < 128 * 64 + 32 * 64 + 128) {
        int q = idx - (128 * 64 + 32 * 64);
        g_bias[q] = b_ih[q] + b_hh[q];
    } else if (idx < 128 * 64 + 32 * 64 + 128 + 160) {
        int q = idx - (128 * 64 + 32 * 64 + 128);
        g_Wxp[q] = Wx[q];
    }
}

// ---------------------------------------------------------------------------
// Init: h = c = 0, M0 = X[0] @ Wx  -> swizzled bf16 hi/lo B tiles
// ---------------------------------------------------------------------------
__global__ __launch_bounds__(256) void init_kernel(const float* __restrict__ X,
                                                   const float* __restrict__ Wx) {
    int idx = blockIdx.x * 256 + threadIdx.x;
    int n = idx >> 5;
    int j = idx & 31;
    g_h[idx] = 0.f;
    g_c[idx] = 0.f;
    float mv = 0.f;
#pragma unroll
    for (int k = 0; k < 5; k++)
        mv += X[n * 5 + k] * Wx[k * HH + j];
    __nv_bfloat16 hi = __float2bfloat16(mv);
    __nv_bfloat16 lo = __float2bfloat16(mv - __bfloat162float(hi));
    int kc = n >> 6;
    uint32_t off = swz((uint32_t)(j * 128 + (n & 63) * 2)) >> 1;
    g_Bhi[kc * BTILE_ELEMS + off] = hi;
    g_Blo[kc * BTILE_ELEMS + off] = lo;
}

// ---------------------------------------------------------------------------
// HMMA GEMM with L2-pinned A (evict_last cache hint on bulk copies)
// ---------------------------------------------------------------------------
__device__ __forceinline__ void copy_chunk(uint32_t sb, int b, int rowtile, int chg,
                                           uint64_t pol) {
    uint32_t base = sb + SMEM_BUF + b * BUF_STRIDE;
    uint32_t mbar = sb + MB_FULL0 + b * 8;
    mbar_expect(mbar, 2 * ATILE_BYTES + 2 * BTILE_BYTES);
    bulk_g2s_hint(base + OFF_AHI, g_Ahi + ((size_t)rowtile * NCH_TOT + chg) * ATILE_ELEMS,
                  ATILE_BYTES, mbar, pol);
    bulk_g2s_hint(base + OFF_ALO, g_Alo + ((size_t)rowtile * NCH_TOT + chg) * ATILE_ELEMS,
                  ATILE_BYTES, mbar, pol);
    bulk_g2s_hint(base + OFF_BHI, g_Bhi + (size_t)chg * BTILE_ELEMS, BTILE_BYTES, mbar, pol);
    bulk_g2s_hint(base + OFF_BLO, g_Blo + (size_t)chg * BTILE_ELEMS, BTILE_BYTES, mbar, pol);
}

__global__ __launch_bounds__(GEMM_THREADS) void gemm_tc() {
    extern __shared__ char smem[];
    uint32_t sb = smem_u32(smem);
    const int tid = threadIdx.x;
    const int wid = tid >> 5;
    const int lid = tid & 31;
    const int rowtile = blockIdx.x;
    const int split = blockIdx.y;

    if (tid == 0) {
        mbar_init(sb + MB_FULL0, 1);
        mbar_init(sb + MB_FULL0 + 8, 1);
    }
    __syncthreads();

    float acc[16];
#pragma unroll
    for (int q = 0; q < 16; q++) acc[q] = 0.f;

    const int arow = (wid << 4) + (lid & 15);
    const uint32_t aRowOff = (uint32_t)arow * 128;
    const uint32_t aSx = (uint32_t)(arow & 7) << 4;
    const uint32_t aHalf = (uint32_t)(lid >> 4) << 4;
    const int bn = ((lid >> 4) << 3) + (lid & 7);
    const uint32_t bRowOff = (uint32_t)bn * 128;
    const uint32_t bSx = (uint32_t)(lid & 7) << 4;
    const uint32_t bHalf = (uint32_t)((lid >> 3) & 1) << 4;

    const int ch0 = split * NCH_PER;
    int fph0 = 0, fph1 = 0;
    uint64_t pol = mkpol_evict_last();
    if (tid == 0) copy_chunk(sb, 0, rowtile, ch0, pol);

    for (int i = 0; i < NCH_PER; i++) {
        const int b = i & 1;
        if (tid == 0 && i + 1 < NCH_PER)
            copy_chunk(sb, b ^ 1, rowtile, ch0 + i + 1, pol);

        if (b == 0) { mbar_wait(sb + MB_FULL0, fph0); fph0 ^= 1; }
        else        { mbar_wait(sb + MB_FULL0 + 8, fph1); fph1 ^= 1; }

        const uint32_t base = sb + SMEM_BUF + b * BUF_STRIDE;
        const uint32_t aBase = base + OFF_AHI + aRowOff;
        const uint32_t aBaseLo = base + OFF_ALO + aRowOff;
        const uint32_t bBaseHi = base + OFF_BHI + bRowOff;
        const uint32_t bBaseLo = base + OFF_BLO + bRowOff;

#pragma unroll
        for (int ks = 0; ks < 4; ks++) {
            const uint32_t ak = ((uint32_t)(ks << 5) | aHalf) ^ aSx;
            const uint32_t bk = ((uint32_t)(ks << 5) | bHalf) ^ bSx;
            uint32_t ah[4], al[4], bh[8], bl[8];
            ldsm4(ah, aBase + ak);
            ldsm4(al, aBaseLo + ak);
            ldsm4(&bh[0], bBaseHi + bk);
            ldsm4(&bh[4], bBaseHi + 16 * 128 + bk);
            ldsm4(&bl[0], bBaseLo + bk);
            ldsm4(&bl[4], bBaseLo + 16 * 128 + bk);
#pragma unroll
            for (int nt = 0; nt < 4; nt++) {
                float* C = acc + nt * 4;
                hmma(C, ah, bh[2 * nt], bh[2 * nt + 1]);
                hmma(C, ah, bl[2 * nt], bl[2 * nt + 1]);
                hmma(C, al, bh[2 * nt], bh[2 * nt + 1]);
            }
        }
        __syncthreads();
    }

    const int g = lid >> 2, tg = lid & 3;
    const int row = rowtile * 128 + (wid << 4) + g;
    float* op = &g_part[split][0];
#pragma unroll
    for (int nt = 0; nt < 4; nt++) {
        int n = nt * 8 + tg * 2;
        *(float2*)&op[(size_t)row * HH + n]       = make_float2(acc[nt * 4], acc[nt * 4 + 1]);
        *(float2*)&op[(size_t)(row + 8) * HH + n] = make_float2(acc[nt * 4 + 2], acc[nt * 4 + 3]);
    }
}

// ---------------------------------------------------------------------------
// Update (R=4 row-blocked, FFMA2) — unchanged from round 11
// ---------------------------------------------------------------------------
__global__ __launch_bounds__(UPD_THREADS) void update_kernel(
    const float* __restrict__ X,
    const float* __restrict__ W_fc,
    const float* __restrict__ b_fc,
    float* __restrict__ out,
    int t)
{
    extern __shared__ float S[];
    const int tid = threadIdx.x;
    const int w = tid >> 5;
    const int j = tid & 31;
    const int row0 = blockIdx.x * UPD_BLKROWS + w * 4;

    float x[4], hv[4], cv[4];
#pragma unroll
    for (int i = 0; i < 4; i++) {
        const int nj = (row0 + i) * HH + j;
        float s0 = g_part[0][nj] + g_part[1][nj];
        float s1 = g_part[2][nj] + g_part[3][nj];
        float s2 = g_part[4][nj] + g_part[5][nj];
        float s3 = g_part[6][nj] + g_part[7][nj];
        x[i] = (s0 + s1) + (s2 + s3);
        hv[i] = g_h[nj];
        cv[i] = g_c[nj];
    }

    {
        const float4* s1 = (const float4*)g_Wg;
        float4* d1 = (float4*)&S[SW_OFF];
        for (int i = tid; i < 128 * 17; i += UPD_THREADS) d1[i] = s1[i];
        const float4* s2 = (const float4*)g_WT;
        float4* d2 = (float4*)&S[SWT_OFF];
        for (int i = tid; i < 32 * 17; i += UPD_THREADS) d2[i] = s2[i];
        if (tid < 160) S[SWX_OFF + tid] = g_Wxp[tid];
        if (tid < 128) S[SB_OFF + tid] = g_bias[tid];
    }

#pragma unroll
    for (int i = 0; i < 4; i++) {
        S[SV_OFF + (w * 4 + i) * 68 + j] = x[i];
        S[SV_OFF + (w * 4 + i) * 68 + 32 + j] = hv[i];
    }
    __syncthreads();

    unsigned long long acc[4][4];
#pragma unroll
    for (int i = 0; i < 4; i++)
#pragma unroll
        for (int g = 0; g < 4; g++) acc[i][g] = 0ull;

#pragma unroll
    for (int q = 0; q < 16; q++) {
        ulonglong2 vv[4], ww[4];
#pragma unroll
        for (int i = 0; i < 4; i++)
            vv[i] = *(const ulonglong2*)&S[SV_OFF + (w * 4 + i) * 68 + 4 * q];
#pragma unroll
        for (int g = 0; g < 4; g++)
            ww[g] = *(const ulonglong2*)&S[SW_OFF + (g * 32 + j) * 68 + 4 * q];
#pragma unroll
        for (int i = 0; i < 4; i++)
#pragma unroll
            for (int g = 0; g < 4; g++) {
                fma2(acc[i][g], vv[i].x, ww[g].x);
                fma2(acc[i][g], vv[i].y, ww[g].y);
            }
    }

    float hn[4], cn[4];
#pragma unroll
    for (int i = 0; i < 4; i++) {
        float gi = pairsum(acc[i][0]) + S[SB_OFF + j];
        float gf = pairsum(acc[i][1]) + S[SB_OFF + 32 + j];
        float gg = pairsum(acc[i][2]) + S[SB_OFF + 64 + j];
        float go = pairsum(acc[i][3]) + S[SB_OFF + 96 + j];
        float si = sigf(gi), sf = sigf(gf), tg = tanhfast(gg), so = sigf(go);
        cn[i] = sf * cv[i] + si * tg;
        hn[i] = so * tanhfast(cn[i]);
        const int nj = (row0 + i) * HH + j;
        g_c[nj] = cn[i];
        g_h[nj] = hn[i];
    }

    if (t == ROLLN - 1) {
#pragma unroll
        for (int i = 0; i < 4; i++) {
            float v = hn[i] * W_fc[j];
#pragma unroll
            for (int o = 16; o > 0; o >>= 1)
                v += __shfl_xor_sync(0xffffffffu, v, o);
            if (j == 0) out[row0 + i] = v + b_fc[0];
        }
    } else {
        __syncwarp();
#pragma unroll
        for (int i = 0; i < 4; i++) {
            S[SV_OFF + (w * 4 + i) * 68 + j] = hn[i];
            S[SV_OFF + (w * 4 + i) * 68 + 32 + j] = cn[i];
        }
        __syncwarp();

        float mv[4];
#pragma unroll
        for (int i = 0; i < 4; i++) {
            const float* xr = X + ((size_t)(t + 1) * NN + row0 + i) * 5;
            float s = xr[0] * S[SWX_OFF + j];
            s += xr[1] * S[SWX_OFF + 32 + j];
            s += xr[2] * S[SWX_OFF + 64 + j];
            s += xr[3] * S[SWX_OFF + 96 + j];
            s += xr[4] * S[SWX_OFF + 128 + j];
            mv[i] = s;
        }
        unsigned long long am[4] = {0ull, 0ull, 0ull, 0ull};
#pragma unroll
        for (int q = 0; q < 16; q++) {
            ulonglong2 wt = *(const ulonglong2*)&S[SWT_OFF + j * 68 + 4 * q];
#pragma unroll
            for (int i = 0; i < 4; i++) {
                ulonglong2 vv = *(const ulonglong2*)&S[SV_OFF + (w * 4 + i) * 68 + 4 * q];
                fma2(am[i], vv.x, wt.x);
                fma2(am[i], vv.y, wt.y);
            }
        }
#pragma unroll
        for (int i = 0; i < 4; i++) {
            mv[i] += pairsum(am[i]);
            S[SMV_OFF + (w * 4 + i) * 33 + j] = mv[i];
        }
        __syncthreads();

#pragma unroll
        for (int k = 0; k < 4; k++) {
            int idx = tid + k * UPD_THREADS;      // 0..1023
            int j2 = idx >> 5, nn = idx & 31;
            float tv = S[SMV_OFF + nn * 33 + j2];
            int n2 = blockIdx.x * UPD_BLKROWS + nn;
            __nv_bfloat16 hi = __float2bfloat16(tv);
            __nv_bfloat16 lo = __float2bfloat16(tv - __bfloat162float(hi));
            int kc = n2 >> 6;
            uint32_t off = swz((uint32_t)(j2 * 128 + (n2 & 63) * 2)) >> 1;
            g_Bhi[kc * BTILE_ELEMS + off] = hi;
            g_Blo[kc * BTILE_ELEMS + off] = lo;
        }
    }
}

// ---------------------------------------------------------------------------
extern "C" void kernel_launch(void* const* d_in, const int* in_sizes, int n_in,
                              void* d_out, int out_size) {
    const float* X    = (const float*)d_in[0];
    const float* A    = (const float*)d_in[1];
    const float* Wx   = (const float*)d_in[2];
    const float* Wh   = (const float*)d_in[3];
    const float* Wc   = (const float*)d_in[4];
    const float* W_ih = (const float*)d_in[5];
    const float* W_hh = (const float*)d_in[6];
    const float* b_ih = (const float*)d_in[7];
    const float* b_hh = (const float*)d_in[8];
    const float* W_fc = (const float*)d_in[9];
    const float* b_fc = (const float*)d_in[10];
    float* out = (float*)d_out;

    cudaFuncSetAttribute(gemm_tc, cudaFuncAttributeMaxDynamicSharedMemorySize, SMEM_DYN);
    cudaFuncSetAttribute(update_kernel, cudaFuncAttributeMaxDynamicSharedMemorySize, UPD_SMEM_BYTES);

    convA_kernel<<<(NN * NN) / 256, 256>>>(A);
    pack_kernel<<<42, 256>>>(Wh, Wc, Wx, W_ih, W_hh, b_ih, b_hh);
    init_kernel<<<(NN * HH) / 256, 256>>>(X, Wx);

    dim3 ggrid(ROWTILES, KSPLITS);
    for (int t = 0; t < ROLLN; t++) {
        gemm_tc<<<ggrid, GEMM_THREADS, SMEM_DYN>>>();
        update_kernel<<<UPD_BLOCKS, UPD_THREADS, UPD_SMEM_BYTES>>>(
            X, W_fc, b_fc, out, t);
    }
}